// round 12
// baseline (speedup 1.0000x reference)
#include <cuda_runtime.h>
#include <math.h>

#define NN   500
#define DEG  16
#define BB   8
#define TT   12
#define HH   64
#define FF   32
#define EE   (NN*DEG)      // 8000
#define BT   (BB*TT)       // 96
#define M1C  16
#define M2C  2
#define DOUT (2*HH*HH)     // 8192
#define PLANE (BT*HH)      // 6144
#define SPITCH 68

// Static scratch (allocation-free)
__device__ int   g_bias_nz;                  // b3 != 0 anywhere?
__device__ float g_c[EE*2];                  // per-edge (c0,c1)
__device__ float g_A[(size_t)NN*PLANE*2];    // src-side planes: [n][m][bt][h]
__device__ float g_Az[(size_t)NN*PLANE];     // src bias plane (only if b3 != 0)
__device__ float g_Bz[(size_t)NN*PLANE];     // dst bias plane (block-local round-trip)

typedef unsigned long long ull;

__device__ __forceinline__ ull dup2(float x) {
    ull r;
    asm("mov.b64 %0, {%1, %1};" : "=l"(r) : "r"(__float_as_uint(x)));
    return r;
}
__device__ __forceinline__ void ffma2(ull& d, ull a, ull b) {
    asm("fma.rn.f32x2 %0, %1, %2, %3;" : "=l"(d) : "l"(a), "l"(b), "l"(d));
}
__device__ __forceinline__ void unpk2(ull v, float& lo, float& hi) {
    unsigned ulo, uhi;
    asm("mov.b64 {%0, %1}, %2;" : "=r"(ulo), "=r"(uhi) : "l"(v));
    lo = __uint_as_float(ulo); hi = __uint_as_float(uhi);
}
__device__ __forceinline__ float sigmoidf_(float x) {
    return __fdividef(1.0f, 1.0f + __expf(-x));
}

// ---------------------------------------------------------------------------
// K2a: src-side projections + edge hypernetwork. grid = N, block = 256.
// Writes g_A[n] (2 planes), g_c (16 edges), g_Az if bias.
// ---------------------------------------------------------------------------
__global__ void __launch_bounds__(256) k2a_src(
        const float* __restrict__ state,
        const float* __restrict__ feature,
        const float* __restrict__ dist,
        const float* __restrict__ W1,
        const float* __restrict__ b1,
        const float* __restrict__ W2,
        const float* __restrict__ b2,
        const float* __restrict__ W3,
        const float* __restrict__ b3,
        const int*   __restrict__ src,
        const int*   __restrict__ dst) {
    int n = blockIdx.x;
    __shared__ float s_sm[BT*SPITCH];
    __shared__ float w_sm[HH*HH];
    int tid = threadIdx.x;

    // bias-nonzero scan
    int nz = 0;
    {
        const float4* b4 = (const float4*)b3;
        for (int i = tid; i < DOUT/4; i += 256) {
            float4 v = __ldg(b4 + i);
            nz |= (v.x != 0.f) | (v.y != 0.f) | (v.z != 0.f) | (v.w != 0.f);
        }
    }
    nz = __syncthreads_or(nz);
    if (tid == 0 && n == 0) g_bias_nz = nz;
    int nm = nz ? 3 : 2;

    for (int idx = tid; idx < BT*HH; idx += 256) {
        int bt = idx >> 6, h = idx & 63;
        s_sm[bt*SPITCH + h] = state[((size_t)bt*NN + n)*HH + h];
    }

    // per-edge hypernetwork for segment n (thread = (edge, unit))
    {
        int el = tid >> 4;
        int m  = tid & 15;
        int e  = n*DEG + el;
        int se = __ldg(src + e);
        int de = __ldg(dst + e);
        float z = __ldg(b1 + m) + __ldg(dist + e) * __ldg(W1 + 2*FF*M1C + m);
        const float* fs = feature + se*FF;
        const float* fd = feature + de*FF;
        #pragma unroll 8
        for (int i = 0; i < FF; i++) {
            z = fmaf(__ldg(fs + i), __ldg(W1 + i*M1C + m), z);
            z = fmaf(__ldg(fd + i), __ldg(W1 + (FF+i)*M1C + m), z);
        }
        float h1 = sigmoidf_(z);
        float p0 = h1 * __ldg(W2 + m*M2C + 0);
        float p1 = h1 * __ldg(W2 + m*M2C + 1);
        #pragma unroll
        for (int mk = 1; mk < 16; mk <<= 1) {
            p0 += __shfl_xor_sync(0xFFFFFFFFu, p0, mk);
            p1 += __shfl_xor_sync(0xFFFFFFFFu, p1, mk);
        }
        if (m == 0) {
            g_c[e*2 + 0] = sigmoidf_(p0 + __ldg(b2 + 0));
            g_c[e*2 + 1] = sigmoidf_(p1 + __ldg(b2 + 1));
        }
    }

    int c4 = (tid & 15) * 4;
    int ty = tid >> 4;
    float o0[6][4];

    for (int mi = 0; mi < nm; mi++) {
        __syncthreads();
        {
            const float* wp = (mi == 0) ? W3 : (mi == 1) ? (W3 + DOUT) : b3;
            for (int idx = tid; idx < HH*HH; idx += 256)
                w_sm[idx] = wp[idx];                 // upper half: base 0
        }
        __syncthreads();

        ull acc[6][2];
        #pragma unroll
        for (int r = 0; r < 6; r++) { acc[r][0] = 0ull; acc[r][1] = 0ull; }

        #pragma unroll 4
        for (int k4 = 0; k4 < 16; k4++) {
            float4 sv[6];
            #pragma unroll
            for (int r = 0; r < 6; r++)
                sv[r] = *(const float4*)&s_sm[(ty + 16*r)*SPITCH + k4*4];
            #pragma unroll
            for (int kk = 0; kk < 4; kk++) {
                int k = k4*4 + kk;
                ulonglong2 wp2 = *(const ulonglong2*)&w_sm[k*HH + c4];
                #pragma unroll
                for (int r = 0; r < 6; r++) {
                    float sval = (kk == 0) ? sv[r].x : (kk == 1) ? sv[r].y
                               : (kk == 2) ? sv[r].z : sv[r].w;
                    ull sd = dup2(sval);
                    ffma2(acc[r][0], wp2.x, sd);
                    ffma2(acc[r][1], wp2.y, sd);
                }
            }
        }

        if (mi == 0) {
            #pragma unroll
            for (int r = 0; r < 6; r++) {
                unpk2(acc[r][0], o0[r][0], o0[r][1]);
                unpk2(acc[r][1], o0[r][2], o0[r][3]);
            }
        } else if (mi == 1) {
            float* outp = g_A + (size_t)n*PLANE*2;
            #pragma unroll
            for (int r = 0; r < 6; r++) {
                int row = ty + 16*r;
                float m1v[4];
                unpk2(acc[r][0], m1v[0], m1v[1]);
                unpk2(acc[r][1], m1v[2], m1v[3]);
                size_t base = (size_t)row*HH + c4;
                *(float4*)(outp + base)         = make_float4(o0[r][0], o0[r][1], o0[r][2], o0[r][3]);
                *(float4*)(outp + PLANE + base) = make_float4(m1v[0], m1v[1], m1v[2], m1v[3]);
            }
        } else {
            float* outp = g_Az + (size_t)n*PLANE;
            #pragma unroll
            for (int r = 0; r < 6; r++) {
                int row = ty + 16*r;
                float zv[4];
                unpk2(acc[r][0], zv[0], zv[1]);
                unpk2(acc[r][1], zv[2], zv[3]);
                *(float4*)(outp + row*HH + c4) = make_float4(zv[0], zv[1], zv[2], zv[3]);
            }
        }
    }
}

// ---------------------------------------------------------------------------
// K23b: per-node dst-side GEMM (y planes -> smem) + combine/softmax/aggregate.
// grid = N, block = 256, dynamic smem = 2*PLANE floats (48KB, via opt-in).
// GEMM phase: s_sm = sm[0..6144), w_sm = sm[6144..10240)   (pitch 64; the
//   sv loads are 16-lane broadcasts, so no padding needed).
// Combine phase: y0 = sm[0..6144), y1 = sm[6144..12288)  (aliases GEMM bufs).
// ---------------------------------------------------------------------------
__device__ __forceinline__ void gemm_pass(const float* __restrict__ wp,
                                          float* s_sm, float* w_sm,
                                          int tid, int c4, int ty,
                                          ull acc[6][2]) {
    __syncthreads();
    for (int idx = tid; idx < HH*HH; idx += 256)
        w_sm[idx] = wp[idx];
    __syncthreads();
    #pragma unroll
    for (int r = 0; r < 6; r++) { acc[r][0] = 0ull; acc[r][1] = 0ull; }
    #pragma unroll 4
    for (int k4 = 0; k4 < 16; k4++) {
        float4 sv[6];
        #pragma unroll
        for (int r = 0; r < 6; r++)
            sv[r] = *(const float4*)&s_sm[(ty + 16*r)*HH + k4*4];
        #pragma unroll
        for (int kk = 0; kk < 4; kk++) {
            int k = k4*4 + kk;
            ulonglong2 wp2 = *(const ulonglong2*)&w_sm[k*HH + c4];
            #pragma unroll
            for (int r = 0; r < 6; r++) {
                float sval = (kk == 0) ? sv[r].x : (kk == 1) ? sv[r].y
                           : (kk == 2) ? sv[r].z : sv[r].w;
                ull sd = dup2(sval);
                ffma2(acc[r][0], wp2.x, sd);
                ffma2(acc[r][1], wp2.y, sd);
            }
        }
    }
}

__global__ void __launch_bounds__(256) k23b_dst_combine(
        const float* __restrict__ state,
        const float* __restrict__ W3,
        const float* __restrict__ b3,
        const float* __restrict__ gate,
        const int*   __restrict__ src,
        const int*   __restrict__ dst,
        float*       __restrict__ out) {
    extern __shared__ float sm[];
    float* s_sm = sm;            // [96][64] (GEMM phase)
    float* w_sm = sm + PLANE;    // [64][64] (GEMM phase)
    __shared__ float c0s[DEG], c1s[DEG];
    __shared__ int   srcs[DEG];
    __shared__ int   sh_dstn;

    int n   = blockIdx.x;
    int tid = threadIdx.x;
    int nz  = g_bias_nz;

    if (tid < DEG) {
        int e = n*DEG + tid;
        srcs[tid] = src[e];
        c0s[tid]  = g_c[e*2 + 0];
        c1s[tid]  = g_c[e*2 + 1];
        if (tid == 0) sh_dstn = dst[n*DEG];
    }
    __syncthreads();
    int dstn = sh_dstn;

    // load s[dstn]
    for (int idx = tid; idx < PLANE; idx += 256) {
        int bt = idx >> 6, h = idx & 63;
        s_sm[idx] = state[((size_t)bt*NN + dstn)*HH + h];
    }

    int c4 = (tid & 15) * 4;
    int ty = tid >> 4;
    float o0[6][4];
    ull acc[6][2];

    // pass m0 (W3 row0, lower half) -> o0 registers
    gemm_pass(W3 + HH*HH, s_sm, w_sm, tid, c4, ty, acc);
    #pragma unroll
    for (int r = 0; r < 6; r++) {
        unpk2(acc[r][0], o0[r][0], o0[r][1]);
        unpk2(acc[r][1], o0[r][2], o0[r][3]);
    }

    // bias pass (cold): -> g_Bz[n] (block-private gmem round-trip)
    if (nz) {
        gemm_pass(b3 + HH*HH, s_sm, w_sm, tid, c4, ty, acc);
        float* outp = g_Bz + (size_t)n*PLANE;
        #pragma unroll
        for (int r = 0; r < 6; r++) {
            int row = ty + 16*r;
            float zv[4];
            unpk2(acc[r][0], zv[0], zv[1]);
            unpk2(acc[r][1], zv[2], zv[3]);
            *(float4*)(outp + row*HH + c4) = make_float4(zv[0], zv[1], zv[2], zv[3]);
        }
    }

    // pass m1 (W3 row1, lower half) -> acc; then both planes -> smem (alias ok)
    gemm_pass(W3 + DOUT + HH*HH, s_sm, w_sm, tid, c4, ty, acc);
    __syncthreads();     // all GEMM reads of s_sm/w_sm done before overwrite
    #pragma unroll
    for (int r = 0; r < 6; r++) {
        int row = ty + 16*r;
        float m1v[4];
        unpk2(acc[r][0], m1v[0], m1v[1]);
        unpk2(acc[r][1], m1v[2], m1v[3]);
        *(float4*)&sm[row*HH + c4]         = make_float4(o0[r][0], o0[r][1], o0[r][2], o0[r][3]);
        *(float4*)&sm[PLANE + row*HH + c4] = make_float4(m1v[0], m1v[1], m1v[2], m1v[3]);
    }
    __syncthreads();

    // ---- combine: 6 bt-tiles of 16 rows ----
    float sg = sigmoidf_(__ldg(gate));
    int h4  = (tid & 15) * 4;
    int rto = tid >> 4;          // 0..15 row-in-tile

    for (int tile = 0; tile < 6; tile++) {
        int bt = tile*16 + rto;
        int off = bt*HH + h4;
        size_t eoff = (size_t)off;

        float4 y0 = *(const float4*)&sm[off];
        float4 y1 = *(const float4*)&sm[PLANE + off];

        float4 num = make_float4(0.f, 0.f, 0.f, 0.f);
        float4 den = make_float4(0.f, 0.f, 0.f, 0.f);

        if (!nz) {
            #pragma unroll
            for (int j = 0; j < DEG; j++) {
                int sj = srcs[j];
                const float* xp = g_A + (size_t)sj*PLANE*2 + eoff;
                float4 x0 = *(const float4*)(xp);
                float4 x1 = *(const float4*)(xp + PLANE);
                float4 s4 = *(const float4*)(state + ((size_t)bt*NN + sj)*HH + h4);
                float c0 = c0s[j], c1 = c1s[j];
                float4 a;
                a.x = fmaf(c0, x0.x + y0.x, c1 * (x1.x + y1.x));
                a.y = fmaf(c0, x0.y + y0.y, c1 * (x1.y + y1.y));
                a.z = fmaf(c0, x0.z + y0.z, c1 * (x1.z + y1.z));
                a.w = fmaf(c0, x0.w + y0.w, c1 * (x1.w + y1.w));
                a.x = fmaxf(a.x, 0.01f*a.x);
                a.y = fmaxf(a.y, 0.01f*a.y);
                a.z = fmaxf(a.z, 0.01f*a.z);
                a.w = fmaxf(a.w, 0.01f*a.w);
                float4 p;
                p.x = __expf(a.x); p.y = __expf(a.y);
                p.z = __expf(a.z); p.w = __expf(a.w);
                den.x += p.x; den.y += p.y; den.z += p.z; den.w += p.w;
                num.x = fmaf(p.x, s4.x, num.x);
                num.y = fmaf(p.y, s4.y, num.y);
                num.z = fmaf(p.z, s4.z, num.z);
                num.w = fmaf(p.w, s4.w, num.w);
            }
        } else {
            float4 y2 = *(const float4*)(g_Bz + (size_t)n*PLANE + eoff);
            #pragma unroll
            for (int j = 0; j < DEG; j++) {
                int sj = srcs[j];
                const float* xp = g_A + (size_t)sj*PLANE*2 + eoff;
                float4 x0 = *(const float4*)(xp);
                float4 x1 = *(const float4*)(xp + PLANE);
                float4 x2 = *(const float4*)(g_Az + (size_t)sj*PLANE + eoff);
                float4 s4 = *(const float4*)(state + ((size_t)bt*NN + sj)*HH + h4);
                float c0 = c0s[j], c1 = c1s[j];
                float4 a;
                a.x = fmaf(c0, x0.x + y0.x, fmaf(c1, x1.x + y1.x, x2.x + y2.x));
                a.y = fmaf(c0, x0.y + y0.y, fmaf(c1, x1.y + y1.y, x2.y + y2.y));
                a.z = fmaf(c0, x0.z + y0.z, fmaf(c1, x1.z + y1.z, x2.z + y2.z));
                a.w = fmaf(c0, x0.w + y0.w, fmaf(c1, x1.w + y1.w, x2.w + y2.w));
                a.x = fmaxf(a.x, 0.01f*a.x);
                a.y = fmaxf(a.y, 0.01f*a.y);
                a.z = fmaxf(a.z, 0.01f*a.z);
                a.w = fmaxf(a.w, 0.01f*a.w);
                float4 p;
                p.x = __expf(a.x); p.y = __expf(a.y);
                p.z = __expf(a.z); p.w = __expf(a.w);
                den.x += p.x; den.y += p.y; den.z += p.z; den.w += p.w;
                num.x = fmaf(p.x, s4.x, num.x);
                num.y = fmaf(p.y, s4.y, num.y);
                num.z = fmaf(p.z, s4.z, num.z);
                num.w = fmaf(p.w, s4.w, num.w);
            }
        }

        float4 o;
        o.x = fmaxf(__fdividef(num.x, den.x), 0.f) * sg;
        o.y = fmaxf(__fdividef(num.y, den.y), 0.f) * sg;
        o.z = fmaxf(__fdividef(num.z, den.z), 0.f) * sg;
        o.w = fmaxf(__fdividef(num.w, den.w), 0.f) * sg;
        *(float4*)(out + ((size_t)bt*NN + n)*HH + h4) = o;
    }
}

// ---------------------------------------------------------------------------
extern "C" void kernel_launch(void* const* d_in, const int* in_sizes, int n_in,
                              void* d_out, int out_size) {
    const float* state   = (const float*)d_in[0];
    const float* feature = (const float*)d_in[1];
    const float* dist    = (const float*)d_in[2];
    const float* W1      = (const float*)d_in[3];
    const float* b1      = (const float*)d_in[4];
    const float* W2      = (const float*)d_in[5];
    const float* b2      = (const float*)d_in[6];
    const float* W3      = (const float*)d_in[7];
    const float* b3      = (const float*)d_in[8];
    const float* gate    = (const float*)d_in[9];
    const int*   src     = (const int*)d_in[10];
    const int*   dst     = (const int*)d_in[11];
    float* out = (float*)d_out;

    // Opt into 48KB+ dynamic smem (proven capture-safe in round 7).
    (void)cudaFuncSetAttribute((const void*)k23b_dst_combine,
                               cudaFuncAttributeMaxDynamicSharedMemorySize,
                               2*PLANE*(int)sizeof(float));

    k2a_src<<<NN, 256>>>(state, feature, dist, W1, b1, W2, b2, W3, b3, src, dst);
    k23b_dst_combine<<<NN, 256, 2*PLANE*sizeof(float)>>>(state, W3, b3, gate,
                                                         src, dst, out);
}

// round 13
// speedup vs baseline: 1.0632x; 1.0632x over previous
#include <cuda_runtime.h>
#include <math.h>

#define NN   500
#define DEG  16
#define BB   8
#define TT   12
#define HH   64
#define FF   32
#define EE   (NN*DEG)      // 8000
#define BT   (BB*TT)       // 96
#define M1C  16
#define M2C  2
#define DOUT (2*HH*HH)     // 8192
#define PLANE (BT*HH)      // 6144

#define SP      68          // s_sm row pitch (floats): conflict-free A frags
#define WPITCH  264         // w_sm row pitch (floats): 256+8, conflict-free B frags
#define K2_SMEM ((BT*SP + HH*WPITCH)*4)   // (6528 + 16896)*4 = 93696 B

// Static scratch (allocation-free)
__device__ int   g_bias_nz;
__device__ float g_c[EE*2];                  // per-edge (c0,c1)
__device__ float g_A[(size_t)NN*PLANE*2];    // src-side planes: [n][m][bt][h]
__device__ float g_B[(size_t)NN*PLANE*2];    // dst-side planes: [n][m][bt][h]
__device__ float g_Az[(size_t)NN*PLANE];     // src bias plane (only if b3 != 0)
__device__ float g_Bz[(size_t)NN*PLANE];     // dst bias plane

__device__ __forceinline__ float sigmoidf_(float x) {
    return __fdividef(1.0f, 1.0f + __expf(-x));
}

// ---- tf32 split + mma helpers --------------------------------------------
__device__ __forceinline__ void split_tf32(float x, unsigned &hi, unsigned &lo) {
    asm("cvt.rna.tf32.f32 %0, %1;" : "=r"(hi) : "f"(x));
    float l = x - __uint_as_float(hi);
    asm("cvt.rna.tf32.f32 %0, %1;" : "=r"(lo) : "f"(l));
}
__device__ __forceinline__ void mma_tf32(float &d0, float &d1, float &d2, float &d3,
        unsigned a0, unsigned a1, unsigned a2, unsigned a3,
        unsigned b0, unsigned b1) {
    asm("mma.sync.aligned.m16n8k8.row.col.f32.tf32.tf32.f32 "
        "{%0,%1,%2,%3}, {%4,%5,%6,%7}, {%8,%9}, {%0,%1,%2,%3};"
        : "+f"(d0), "+f"(d1), "+f"(d2), "+f"(d3)
        : "r"(a0), "r"(a1), "r"(a2), "r"(a3), "r"(b0), "r"(b1));
}

// ---------------------------------------------------------------------------
// K2TC: per-node projections via 3xTF32 tensor-core GEMM.
//   grid = N, block = 512 (16 warps).
//   Computes P = s[n][96,64] @ Wc[64,256], Wc cols = [X0|X1|Y0|Y1]
//   (X = W3 upper half -> g_A planes; Y = W3 lower half -> g_B planes).
//   Warp w: m-tiles (w&1)*3+{0,1,2}, n-tiles (w>>1)*4+{0..3}.
//   Also: edge hypernetwork (tid<256), bias planes (cold, scalar).
// ---------------------------------------------------------------------------
__global__ void __launch_bounds__(512) k2tc(
        const float* __restrict__ state,
        const float* __restrict__ feature,
        const float* __restrict__ dist,
        const float* __restrict__ W1,
        const float* __restrict__ b1,
        const float* __restrict__ W2,
        const float* __restrict__ b2,
        const float* __restrict__ W3,
        const float* __restrict__ b3,
        const int*   __restrict__ src,
        const int*   __restrict__ dst) {
    extern __shared__ float sm[];
    float* s_sm = sm;                 // [96][SP]
    float* w_sm = sm + BT*SP;         // [64][WPITCH]

    int n   = blockIdx.x;
    int tid = threadIdx.x;

    // ---- bias-nonzero scan ----
    int nz = 0;
    {
        const float4* b4 = (const float4*)b3;
        for (int i = tid; i < DOUT/4; i += 512) {
            float4 v = __ldg(b4 + i);
            nz |= (v.x != 0.f) | (v.y != 0.f) | (v.z != 0.f) | (v.w != 0.f);
        }
    }
    nz = __syncthreads_or(nz);
    if (tid == 0 && n == 0) g_bias_nz = nz;

    // ---- load s[n] (padded pitch) ----
    for (int idx = tid; idx < BT*HH; idx += 512) {
        int bt = idx >> 6, h = idx & 63;
        s_sm[bt*SP + h] = state[((size_t)bt*NN + n)*HH + h];
    }
    // ---- load Wc: w_sm[k][mat*64+h], mat = (half<<1 ordering: 0=X0,1=X1,2=Y0,3=Y1)
    {
        const float4* w4 = (const float4*)W3;
        for (int i4 = tid; i4 < (4*HH*HH)/4; i4 += 512) {
            int idx  = i4 * 4;
            int mat  = idx >> 12;           // 0..3
            int rem  = idx & 4095;
            int k    = rem >> 6;
            int h    = rem & 63;
            int m    = mat & 1;             // which W3 row
            int half = mat >> 1;            // upper/lower
            float4 v = __ldg((const float4*)(W3 + (size_t)m*DOUT + (half*HH + k)*HH + h));
            *(float4*)&w_sm[k*WPITCH + mat*HH + h] = v;
        }
        (void)w4;
    }

    // ---- edge hypernetwork (tid < 256): thread = (edge, unit) ----
    if (tid < 256) {
        int el = tid >> 4;
        int m  = tid & 15;
        int e  = n*DEG + el;
        int se = __ldg(src + e);
        int de = __ldg(dst + e);
        float z = __ldg(b1 + m) + __ldg(dist + e) * __ldg(W1 + 2*FF*M1C + m);
        const float* fs = feature + se*FF;
        const float* fd = feature + de*FF;
        #pragma unroll 8
        for (int i = 0; i < FF; i++) {
            z = fmaf(__ldg(fs + i), __ldg(W1 + i*M1C + m), z);
            z = fmaf(__ldg(fd + i), __ldg(W1 + (FF+i)*M1C + m), z);
        }
        float h1 = sigmoidf_(z);
        float p0 = h1 * __ldg(W2 + m*M2C + 0);
        float p1 = h1 * __ldg(W2 + m*M2C + 1);
        #pragma unroll
        for (int mk = 1; mk < 16; mk <<= 1) {
            p0 += __shfl_xor_sync(0xFFFFFFFFu, p0, mk);
            p1 += __shfl_xor_sync(0xFFFFFFFFu, p1, mk);
        }
        if (m == 0) {
            g_c[e*2 + 0] = sigmoidf_(p0 + __ldg(b2 + 0));
            g_c[e*2 + 1] = sigmoidf_(p1 + __ldg(b2 + 1));
        }
    }
    __syncthreads();

    // ---- tensor-core GEMM ----
    int wid    = tid >> 5;
    int lane   = tid & 31;
    int gid    = lane >> 2;     // 0..7
    int tig    = lane & 3;      // 0..3
    int mgroup = wid & 1;       // 3 m-tiles each
    int ngroup = wid >> 1;      // 0..7, 4 n-tiles each

    float acc[3][4][4];
    #pragma unroll
    for (int mi = 0; mi < 3; mi++)
        #pragma unroll
        for (int ni = 0; ni < 4; ni++)
            #pragma unroll
            for (int q = 0; q < 4; q++) acc[mi][ni][q] = 0.f;

    #pragma unroll
    for (int ks = 0; ks < 8; ks++) {
        unsigned ah[3][4], al[3][4];
        #pragma unroll
        for (int mi = 0; mi < 3; mi++) {
            int row0 = (mgroup*3 + mi)*16 + gid;
            int kc   = ks*8 + tig;
            split_tf32(s_sm[row0*SP + kc],           ah[mi][0], al[mi][0]);
            split_tf32(s_sm[(row0+8)*SP + kc],       ah[mi][1], al[mi][1]);
            split_tf32(s_sm[row0*SP + kc + 4],       ah[mi][2], al[mi][2]);
            split_tf32(s_sm[(row0+8)*SP + kc + 4],   ah[mi][3], al[mi][3]);
        }
        unsigned bh[4][2], bl[4][2];
        #pragma unroll
        for (int ni = 0; ni < 4; ni++) {
            int c = (ngroup*4 + ni)*8 + gid;
            split_tf32(w_sm[(ks*8 + tig)*WPITCH + c],     bh[ni][0], bl[ni][0]);
            split_tf32(w_sm[(ks*8 + tig + 4)*WPITCH + c], bh[ni][1], bl[ni][1]);
        }
        #pragma unroll
        for (int mi = 0; mi < 3; mi++)
            #pragma unroll
            for (int ni = 0; ni < 4; ni++) {
                float* d = acc[mi][ni];
                mma_tf32(d[0], d[1], d[2], d[3],
                         ah[mi][0], ah[mi][1], ah[mi][2], ah[mi][3],
                         bh[ni][0], bh[ni][1]);
                mma_tf32(d[0], d[1], d[2], d[3],
                         al[mi][0], al[mi][1], al[mi][2], al[mi][3],
                         bh[ni][0], bh[ni][1]);
                mma_tf32(d[0], d[1], d[2], d[3],
                         ah[mi][0], ah[mi][1], ah[mi][2], ah[mi][3],
                         bl[ni][0], bl[ni][1]);
            }
    }

    // ---- stores: mat = nt>>3 selects plane ----
    #pragma unroll
    for (int ni = 0; ni < 4; ni++) {
        int nt  = ngroup*4 + ni;
        int mat = nt >> 3;              // 0..3
        int h   = (nt*8 + 2*tig) & 63;
        float* plane = ((mat < 2) ? g_A : g_B) + (size_t)n*PLANE*2 + (mat & 1)*PLANE;
        #pragma unroll
        for (int mi = 0; mi < 3; mi++) {
            int row = (mgroup*3 + mi)*16 + gid;
            float* d = acc[mi][ni];
            *(float2*)(plane + row*HH + h)     = make_float2(d[0], d[1]);
            *(float2*)(plane + (row+8)*HH + h) = make_float2(d[2], d[3]);
        }
    }

    // ---- bias planes (cold path, scalar) ----
    if (nz) {
        for (int idx = tid; idx < 2*PLANE; idx += 512) {
            int half = idx >= PLANE;
            int rem  = idx - half*PLANE;
            int bt   = rem >> 6, h = rem & 63;
            float acc2 = 0.f;
            #pragma unroll 8
            for (int k = 0; k < HH; k++)
                acc2 = fmaf(s_sm[bt*SP + k], __ldg(b3 + (half*HH + k)*HH + h), acc2);
            (half ? g_Bz : g_Az)[(size_t)n*PLANE + bt*HH + h] = acc2;
        }
    }
}

// ---------------------------------------------------------------------------
// K3: combine + single-pass softmax + aggregate. grid = N*6 bt-tiles.
// (round-9 version, measured 40.8us)
// ---------------------------------------------------------------------------
__global__ void __launch_bounds__(256, 4) k3_combine(
        const float* __restrict__ state,
        const float* __restrict__ gate,
        const int*   __restrict__ src,
        const int*   __restrict__ dst,
        float*       __restrict__ out) {
    int n    = blockIdx.x / 6;
    int tile = blockIdx.x % 6;

    __shared__ float c0s[DEG], c1s[DEG];
    __shared__ int   srcs[DEG];
    __shared__ int   dstn_s;
    int tid = threadIdx.x;
    if (tid < DEG) {
        int e = n*DEG + tid;
        srcs[tid] = src[e];
        c0s[tid]  = g_c[e*2 + 0];
        c1s[tid]  = g_c[e*2 + 1];
        if (tid == 0) dstn_s = dst[n*DEG];
    }
    int bias_nz = g_bias_nz;
    __syncthreads();

    int dstn = dstn_s;
    int h4   = (tid & 15) * 4;
    int bt   = tile*16 + (tid >> 4);
    size_t eoff = (size_t)bt*HH + h4;

    const float* yp = g_B + (size_t)dstn*PLANE*2 + eoff;
    float4 y0 = *(const float4*)(yp);
    float4 y1 = *(const float4*)(yp + PLANE);

    float4 num = make_float4(0.f, 0.f, 0.f, 0.f);
    float4 den = make_float4(0.f, 0.f, 0.f, 0.f);

    if (!bias_nz) {
        #pragma unroll
        for (int j = 0; j < DEG; j++) {
            int sj = srcs[j];
            const float* xp = g_A + (size_t)sj*PLANE*2 + eoff;
            float4 x0 = *(const float4*)(xp);
            float4 x1 = *(const float4*)(xp + PLANE);
            float4 s4 = *(const float4*)(state + ((size_t)bt*NN + sj)*HH + h4);
            float c0 = c0s[j], c1 = c1s[j];
            float4 a;
            a.x = fmaf(c0, x0.x + y0.x, c1 * (x1.x + y1.x));
            a.y = fmaf(c0, x0.y + y0.y, c1 * (x1.y + y1.y));
            a.z = fmaf(c0, x0.z + y0.z, c1 * (x1.z + y1.z));
            a.w = fmaf(c0, x0.w + y0.w, c1 * (x1.w + y1.w));
            a.x = fmaxf(a.x, 0.01f*a.x);
            a.y = fmaxf(a.y, 0.01f*a.y);
            a.z = fmaxf(a.z, 0.01f*a.z);
            a.w = fmaxf(a.w, 0.01f*a.w);
            float4 p;
            p.x = __expf(a.x); p.y = __expf(a.y);
            p.z = __expf(a.z); p.w = __expf(a.w);
            den.x += p.x; den.y += p.y; den.z += p.z; den.w += p.w;
            num.x = fmaf(p.x, s4.x, num.x);
            num.y = fmaf(p.y, s4.y, num.y);
            num.z = fmaf(p.z, s4.z, num.z);
            num.w = fmaf(p.w, s4.w, num.w);
        }
    } else {
        float4 y2 = *(const float4*)(g_Bz + (size_t)dstn*PLANE + eoff);
        #pragma unroll
        for (int j = 0; j < DEG; j++) {
            int sj = srcs[j];
            const float* xp = g_A + (size_t)sj*PLANE*2 + eoff;
            float4 x0 = *(const float4*)(xp);
            float4 x1 = *(const float4*)(xp + PLANE);
            float4 x2 = *(const float4*)(g_Az + (size_t)sj*PLANE + eoff);
            float4 s4 = *(const float4*)(state + ((size_t)bt*NN + sj)*HH + h4);
            float c0 = c0s[j], c1 = c1s[j];
            float4 a;
            a.x = fmaf(c0, x0.x + y0.x, fmaf(c1, x1.x + y1.x, x2.x + y2.x));
            a.y = fmaf(c0, x0.y + y0.y, fmaf(c1, x1.y + y1.y, x2.y + y2.y));
            a.z = fmaf(c0, x0.z + y0.z, fmaf(c1, x1.z + y1.z, x2.z + y2.z));
            a.w = fmaf(c0, x0.w + y0.w, fmaf(c1, x1.w + y1.w, x2.w + y2.w));
            a.x = fmaxf(a.x, 0.01f*a.x);
            a.y = fmaxf(a.y, 0.01f*a.y);
            a.z = fmaxf(a.z, 0.01f*a.z);
            a.w = fmaxf(a.w, 0.01f*a.w);
            float4 p;
            p.x = __expf(a.x); p.y = __expf(a.y);
            p.z = __expf(a.z); p.w = __expf(a.w);
            den.x += p.x; den.y += p.y; den.z += p.z; den.w += p.w;
            num.x = fmaf(p.x, s4.x, num.x);
            num.y = fmaf(p.y, s4.y, num.y);
            num.z = fmaf(p.z, s4.z, num.z);
            num.w = fmaf(p.w, s4.w, num.w);
        }
    }

    float sg = sigmoidf_(gate[0]);
    float4 o;
    o.x = fmaxf(__fdividef(num.x, den.x), 0.f) * sg;
    o.y = fmaxf(__fdividef(num.y, den.y), 0.f) * sg;
    o.z = fmaxf(__fdividef(num.z, den.z), 0.f) * sg;
    o.w = fmaxf(__fdividef(num.w, den.w), 0.f) * sg;
    *(float4*)(out + ((size_t)bt*NN + n)*HH + h4) = o;
}

// ---------------------------------------------------------------------------
extern "C" void kernel_launch(void* const* d_in, const int* in_sizes, int n_in,
                              void* d_out, int out_size) {
    const float* state   = (const float*)d_in[0];
    const float* feature = (const float*)d_in[1];
    const float* dist    = (const float*)d_in[2];
    const float* W1      = (const float*)d_in[3];
    const float* b1      = (const float*)d_in[4];
    const float* W2      = (const float*)d_in[5];
    const float* b2      = (const float*)d_in[6];
    const float* W3      = (const float*)d_in[7];
    const float* b3      = (const float*)d_in[8];
    const float* gate    = (const float*)d_in[9];
    const int*   src     = (const int*)d_in[10];
    const int*   dst     = (const int*)d_in[11];
    float* out = (float*)d_out;

    // 91.5KB dynamic smem opt-in (capture-safe, proven in round 7).
    (void)cudaFuncSetAttribute((const void*)k2tc,
                               cudaFuncAttributeMaxDynamicSharedMemorySize,
                               K2_SMEM);

    k2tc<<<NN, 512, K2_SMEM>>>(state, feature, dist, W1, b1, W2, b2,
                               W3, b3, src, dst);
    k3_combine<<<NN*6, 256>>>(state, gate, src, dst, out);
}

// round 14
// speedup vs baseline: 1.1423x; 1.0744x over previous
#include <cuda_runtime.h>
#include <math.h>

#define NN   500
#define DEG  16
#define BB   8
#define TT   12
#define HH   64
#define FF   32
#define EE   (NN*DEG)      // 8000
#define BT   (BB*TT)       // 96
#define M1C  16
#define M2C  2
#define DOUT (2*HH*HH)     // 8192
#define PLANE (BT*HH)      // 6144
#define SPITCH 68
#define LOG2E 1.4426950408889634f

// Static scratch (allocation-free)
__device__ int   g_bias_nz;                  // b3 != 0 anywhere?
__device__ float g_c[EE*2];                  // per-edge (c0,c1)
__device__ float g_A[(size_t)NN*PLANE*2];    // src-side planes: [n][m][bt][h]
__device__ float g_B[(size_t)NN*PLANE*2];    // dst-side planes: [n][m][bt][h]
__device__ float g_Az[(size_t)NN*PLANE];     // src bias plane (only if b3 != 0)
__device__ float g_Bz[(size_t)NN*PLANE];     // dst bias plane

typedef unsigned long long ull;

__device__ __forceinline__ ull dup2(float x) {
    ull r;
    asm("mov.b64 %0, {%1, %1};" : "=l"(r) : "r"(__float_as_uint(x)));
    return r;
}
__device__ __forceinline__ void ffma2(ull& d, ull a, ull b) {
    asm("fma.rn.f32x2 %0, %1, %2, %3;" : "=l"(d) : "l"(a), "l"(b), "l"(d));
}
__device__ __forceinline__ ull add2(ull a, ull b) {
    ull r;
    asm("add.rn.f32x2 %0, %1, %2;" : "=l"(r) : "l"(a), "l"(b));
    return r;
}
__device__ __forceinline__ ull mul2(ull a, ull b) {
    ull r;
    asm("mul.rn.f32x2 %0, %1, %2;" : "=l"(r) : "l"(a), "l"(b));
    return r;
}
__device__ __forceinline__ ull fma2r(ull a, ull b, ull c) {
    ull r;
    asm("fma.rn.f32x2 %0, %1, %2, %3;" : "=l"(r) : "l"(a), "l"(b), "l"(c));
    return r;
}
__device__ __forceinline__ void unpk2(ull v, float& lo, float& hi) {
    unsigned ulo, uhi;
    asm("mov.b64 {%0, %1}, %2;" : "=r"(ulo), "=r"(uhi) : "l"(v));
    lo = __uint_as_float(ulo); hi = __uint_as_float(uhi);
}
__device__ __forceinline__ ull pk2(float lo, float hi) {
    ull r;
    asm("mov.b64 %0, {%1, %2};" : "=l"(r) : "r"(__float_as_uint(lo)), "r"(__float_as_uint(hi)));
    return r;
}
__device__ __forceinline__ float ex2f(float x) {
    float r;
    asm("ex2.approx.f32 %0, %1;" : "=f"(r) : "f"(x));
    return r;
}
__device__ __forceinline__ float sigmoidf_(float x) {
    return __fdividef(1.0f, 1.0f + __expf(-x));
}

// ---------------------------------------------------------------------------
// K2: per-(node, side) projections. grid = 2N, block = 256. (round-8 version,
// measured at the fp32-pipe floor ~46us)
// ---------------------------------------------------------------------------
__global__ void __launch_bounds__(256) k2_precompute(
        const float* __restrict__ state,
        const float* __restrict__ feature,
        const float* __restrict__ dist,
        const float* __restrict__ W1,
        const float* __restrict__ b1,
        const float* __restrict__ W2,
        const float* __restrict__ b2,
        const float* __restrict__ W3,
        const float* __restrict__ b3,
        const int*   __restrict__ src,
        const int*   __restrict__ dst) {
    int bid  = blockIdx.x;
    int n    = bid >> 1;
    int side = bid & 1;
    __shared__ float s_sm[BT*SPITCH];   // 26112 B
    __shared__ float w_sm[HH*HH];       // 16384 B
    int tid = threadIdx.x;

    // bias-nonzero scan
    int nz = 0;
    {
        const float4* b4 = (const float4*)b3;
        for (int i = tid; i < DOUT/4; i += 256) {
            float4 v = __ldg(b4 + i);
            nz |= (v.x != 0.f) | (v.y != 0.f) | (v.z != 0.f) | (v.w != 0.f);
        }
    }
    nz = __syncthreads_or(nz);
    if (tid == 0 && bid == 0) g_bias_nz = nz;
    int nm = nz ? 3 : 2;

    for (int idx = tid; idx < BT*HH; idx += 256) {
        int bt = idx >> 6, h = idx & 63;
        s_sm[bt*SPITCH + h] = state[((size_t)bt*NN + n)*HH + h];
    }

    // side 0: per-edge hypernetwork (thread = (edge, unit))
    if (side == 0) {
        int el = tid >> 4;
        int m  = tid & 15;
        int e  = n*DEG + el;
        int se = __ldg(src + e);
        int de = __ldg(dst + e);
        float z = __ldg(b1 + m) + __ldg(dist + e) * __ldg(W1 + 2*FF*M1C + m);
        const float* fs = feature + se*FF;
        const float* fd = feature + de*FF;
        #pragma unroll 8
        for (int i = 0; i < FF; i++) {
            z = fmaf(__ldg(fs + i), __ldg(W1 + i*M1C + m), z);
            z = fmaf(__ldg(fd + i), __ldg(W1 + (FF+i)*M1C + m), z);
        }
        float h1 = sigmoidf_(z);
        float p0 = h1 * __ldg(W2 + m*M2C + 0);
        float p1 = h1 * __ldg(W2 + m*M2C + 1);
        #pragma unroll
        for (int mk = 1; mk < 16; mk <<= 1) {
            p0 += __shfl_xor_sync(0xFFFFFFFFu, p0, mk);
            p1 += __shfl_xor_sync(0xFFFFFFFFu, p1, mk);
        }
        if (m == 0) {
            g_c[e*2 + 0] = sigmoidf_(p0 + __ldg(b2 + 0));
            g_c[e*2 + 1] = sigmoidf_(p1 + __ldg(b2 + 1));
        }
    }

    int c4 = (tid & 15) * 4;
    int ty = tid >> 4;
    float o0[6][4];

    for (int mi = 0; mi < nm; mi++) {
        __syncthreads();
        {
            const float* wp = (mi == 0) ? W3 : (mi == 1) ? (W3 + DOUT) : b3;
            int base = side ? HH*HH : 0;
            for (int idx = tid; idx < HH*HH; idx += 256)
                w_sm[idx] = wp[base + idx];
        }
        __syncthreads();

        ull acc[6][2];
        #pragma unroll
        for (int r = 0; r < 6; r++) { acc[r][0] = 0ull; acc[r][1] = 0ull; }

        #pragma unroll 4
        for (int k4 = 0; k4 < 16; k4++) {
            float4 sv[6];
            #pragma unroll
            for (int r = 0; r < 6; r++)
                sv[r] = *(const float4*)&s_sm[(ty + 16*r)*SPITCH + k4*4];
            #pragma unroll
            for (int kk = 0; kk < 4; kk++) {
                int k = k4*4 + kk;
                ulonglong2 wp2 = *(const ulonglong2*)&w_sm[k*HH + c4];
                #pragma unroll
                for (int r = 0; r < 6; r++) {
                    float sval = (kk == 0) ? sv[r].x : (kk == 1) ? sv[r].y
                               : (kk == 2) ? sv[r].z : sv[r].w;
                    ull sd = dup2(sval);
                    ffma2(acc[r][0], wp2.x, sd);
                    ffma2(acc[r][1], wp2.y, sd);
                }
            }
        }

        if (mi == 0) {
            #pragma unroll
            for (int r = 0; r < 6; r++) {
                unpk2(acc[r][0], o0[r][0], o0[r][1]);
                unpk2(acc[r][1], o0[r][2], o0[r][3]);
            }
        } else if (mi == 1) {
            float* outp = (side ? g_B : g_A) + (size_t)n*PLANE*2;
            #pragma unroll
            for (int r = 0; r < 6; r++) {
                int row = ty + 16*r;
                float m1v[4];
                unpk2(acc[r][0], m1v[0], m1v[1]);
                unpk2(acc[r][1], m1v[2], m1v[3]);
                size_t base = (size_t)row*HH + c4;
                *(float4*)(outp + base)         = make_float4(o0[r][0], o0[r][1], o0[r][2], o0[r][3]);
                *(float4*)(outp + PLANE + base) = make_float4(m1v[0], m1v[1], m1v[2], m1v[3]);
            }
        } else {
            float* outp = (side ? g_Bz : g_Az) + (size_t)n*PLANE;
            #pragma unroll
            for (int r = 0; r < 6; r++) {
                int row = ty + 16*r;
                float zv[4];
                unpk2(acc[r][0], zv[0], zv[1]);
                unpk2(acc[r][1], zv[2], zv[3]);
                *(float4*)(outp + row*HH + c4) = make_float4(zv[0], zv[1], zv[2], zv[3]);
            }
        }
    }
}

// ---------------------------------------------------------------------------
// K3: combine + single-pass softmax + aggregate. grid = N*6 bt-tiles.
// f32x2-packed elementwise math; log2e folded into edge coefficients so
// exp() is a bare ex2 (exact rewrite: 2^(a*log2e) = e^a; max commutes with
// positive scaling).
// ---------------------------------------------------------------------------
__global__ void __launch_bounds__(256, 4) k3_combine(
        const float* __restrict__ state,
        const float* __restrict__ gate,
        const int*   __restrict__ src,
        const int*   __restrict__ dst,
        float*       __restrict__ out) {
    int n    = blockIdx.x / 6;
    int tile = blockIdx.x % 6;

    __shared__ ull  c0d[DEG], c1d[DEG];   // per-edge packed (c*log2e, c*log2e)
    __shared__ int  srcs[DEG];
    __shared__ int  dstn_s;
    int tid = threadIdx.x;
    if (tid < DEG) {
        int e = n*DEG + tid;
        srcs[tid] = src[e];
        c0d[tid]  = dup2(g_c[e*2 + 0] * LOG2E);
        c1d[tid]  = dup2(g_c[e*2 + 1] * LOG2E);
        if (tid == 0) dstn_s = dst[n*DEG];
    }
    int bias_nz = g_bias_nz;
    __syncthreads();

    int dstn = dstn_s;
    int h4   = (tid & 15) * 4;
    int bt   = tile*16 + (tid >> 4);
    size_t eoff = (size_t)bt*HH + h4;

    const float* yp = g_B + (size_t)dstn*PLANE*2 + eoff;
    ulonglong2 y0 = *(const ulonglong2*)(yp);
    ulonglong2 y1 = *(const ulonglong2*)(yp + PLANE);

    const float* xbase  = g_A + eoff;                       // + sj*PLANE*2
    const float* stbase = state + (size_t)bt*NN*HH + h4;    // + sj*HH

    ull numA = 0ull, numB = 0ull, denA = 0ull, denB = 0ull;

    if (!bias_nz) {
        #pragma unroll
        for (int j = 0; j < DEG; j++) {
            int sj = srcs[j];
            const float* xp = xbase + (size_t)sj*(PLANE*2);
            ulonglong2 x0 = *(const ulonglong2*)(xp);
            ulonglong2 x1 = *(const ulonglong2*)(xp + PLANE);
            ulonglong2 s4 = *(const ulonglong2*)(stbase + (size_t)sj*HH);
            ull c0 = c0d[j], c1 = c1d[j];
            // a*log2e (packed)
            ull aA = fma2r(c0, add2(x0.x, y0.x), mul2(c1, add2(x1.x, y1.x)));
            ull aB = fma2r(c0, add2(x0.y, y0.y), mul2(c1, add2(x1.y, y1.y)));
            float a0, a1, a2, a3;
            unpk2(aA, a0, a1);
            unpk2(aB, a2, a3);
            a0 = fmaxf(a0, 0.01f*a0);
            a1 = fmaxf(a1, 0.01f*a1);
            a2 = fmaxf(a2, 0.01f*a2);
            a3 = fmaxf(a3, 0.01f*a3);
            float p0 = ex2f(a0), p1 = ex2f(a1), p2 = ex2f(a2), p3 = ex2f(a3);
            ull pA = pk2(p0, p1), pB = pk2(p2, p3);
            denA = add2(denA, pA);
            denB = add2(denB, pB);
            numA = fma2r(pA, s4.x, numA);
            numB = fma2r(pB, s4.y, numB);
        }
    } else {
        const ull L2 = dup2(LOG2E);
        const float* y2p = g_Bz + (size_t)dstn*PLANE + eoff;
        ulonglong2 y2 = *(const ulonglong2*)(y2p);
        #pragma unroll
        for (int j = 0; j < DEG; j++) {
            int sj = srcs[j];
            const float* xp = xbase + (size_t)sj*(PLANE*2);
            ulonglong2 x0 = *(const ulonglong2*)(xp);
            ulonglong2 x1 = *(const ulonglong2*)(xp + PLANE);
            ulonglong2 x2 = *(const ulonglong2*)(g_Az + (size_t)sj*PLANE + eoff);
            ulonglong2 s4 = *(const ulonglong2*)(stbase + (size_t)sj*HH);
            ull c0 = c0d[j], c1 = c1d[j];
            ull bA = fma2r(L2, add2(x2.x, y2.x), mul2(c1, add2(x1.x, y1.x)));
            ull bB = fma2r(L2, add2(x2.y, y2.y), mul2(c1, add2(x1.y, y1.y)));
            ull aA = fma2r(c0, add2(x0.x, y0.x), bA);
            ull aB = fma2r(c0, add2(x0.y, y0.y), bB);
            float a0, a1, a2, a3;
            unpk2(aA, a0, a1);
            unpk2(aB, a2, a3);
            a0 = fmaxf(a0, 0.01f*a0);
            a1 = fmaxf(a1, 0.01f*a1);
            a2 = fmaxf(a2, 0.01f*a2);
            a3 = fmaxf(a3, 0.01f*a3);
            float p0 = ex2f(a0), p1 = ex2f(a1), p2 = ex2f(a2), p3 = ex2f(a3);
            ull pA = pk2(p0, p1), pB = pk2(p2, p3);
            denA = add2(denA, pA);
            denB = add2(denB, pB);
            numA = fma2r(pA, s4.x, numA);
            numB = fma2r(pB, s4.y, numB);
        }
    }

    float sg = sigmoidf_(gate[0]);
    float n0, n1, n2, n3, d0, d1, d2, d3;
    unpk2(numA, n0, n1);
    unpk2(numB, n2, n3);
    unpk2(denA, d0, d1);
    unpk2(denB, d2, d3);
    float4 o;
    o.x = fmaxf(__fdividef(n0, d0), 0.f) * sg;
    o.y = fmaxf(__fdividef(n1, d1), 0.f) * sg;
    o.z = fmaxf(__fdividef(n2, d2), 0.f) * sg;
    o.w = fmaxf(__fdividef(n3, d3), 0.f) * sg;
    *(float4*)(out + ((size_t)bt*NN + n)*HH + h4) = o;
}

// ---------------------------------------------------------------------------
extern "C" void kernel_launch(void* const* d_in, const int* in_sizes, int n_in,
                              void* d_out, int out_size) {
    const float* state   = (const float*)d_in[0];
    const float* feature = (const float*)d_in[1];
    const float* dist    = (const float*)d_in[2];
    const float* W1      = (const float*)d_in[3];
    const float* b1      = (const float*)d_in[4];
    const float* W2      = (const float*)d_in[5];
    const float* b2      = (const float*)d_in[6];
    const float* W3      = (const float*)d_in[7];
    const float* b3      = (const float*)d_in[8];
    const float* gate    = (const float*)d_in[9];
    const int*   src     = (const int*)d_in[10];
    const int*   dst     = (const int*)d_in[11];
    float* out = (float*)d_out;

    k2_precompute<<<NN*2, 256>>>(state, feature, dist, W1, b1, W2, b2,
                                 W3, b3, src, dst);
    k3_combine<<<NN*6, 256>>>(state, gate, src, dst, out);
}